// round 3
// baseline (speedup 1.0000x reference)
#include <cuda_runtime.h>
#include <cuda_bf16.h>
#include <stdint.h>

#define B_   4096
#define I_   256
#define H_   1024
#define N4H  4096
#define M_   4

// ---------------- scratch (device globals; no runtime allocation) ----------
__device__ float g_weff_ih[M_ * I_ * N4H];   // 16 MB
__device__ float g_weff_hh[M_ * H_ * N4H];   // 64 MB
__device__ float g_bq_ih[M_ * N4H];
__device__ float g_bn_ih[M_ * N4H];
__device__ float g_bq_hh[M_ * N4H];
__device__ float g_bn_hh[M_ * N4H];
__device__ unsigned char g_code_in[B_ * I_]; // 1 MB
__device__ unsigned char g_code_hx[B_ * H_]; // 4 MB
__device__ float g_gates[(size_t)B_ * N4H];  // 64 MB
__device__ float g_max[4];                   // wih, whh, bih, bhh

// ---------------- threefry2x32 (JAX exact) ---------------------------------
__host__ __device__ __forceinline__ uint32_t rotl32(uint32_t x, int r) {
    return (x << r) | (x >> (32 - r));
}

__host__ __device__ __forceinline__ void tf2x32(uint32_t k0, uint32_t k1,
                                                uint32_t x0, uint32_t x1,
                                                uint32_t* o0, uint32_t* o1) {
    uint32_t ks0 = k0, ks1 = k1, ks2 = k0 ^ k1 ^ 0x1BD11BDAu;
    x0 += ks0; x1 += ks1;
#define TF_RND(r) { x0 += x1; x1 = rotl32(x1, r); x1 ^= x0; }
    TF_RND(13) TF_RND(15) TF_RND(26) TF_RND(6)
    x0 += ks1; x1 += ks2 + 1u;
    TF_RND(17) TF_RND(29) TF_RND(16) TF_RND(24)
    x0 += ks2; x1 += ks0 + 2u;
    TF_RND(13) TF_RND(15) TF_RND(26) TF_RND(6)
    x0 += ks0; x1 += ks1 + 3u;
    TF_RND(17) TF_RND(29) TF_RND(16) TF_RND(24)
    x0 += ks1; x1 += ks2 + 4u;
    TF_RND(13) TF_RND(15) TF_RND(26) TF_RND(6)
    x0 += ks2; x1 += ks0 + 5u;
#undef TF_RND
    *o0 = x0; *o1 = x1;
}

// ---------------- XLA erf_inv (f32 Giles polynomial) ------------------------
__device__ __forceinline__ float erfinv_xla(float x) {
    float w = -log1pf(-__fmul_rn(x, x));
    float p;
    if (w < 5.0f) {
        w = w - 2.5f;
        p = 2.81022636e-08f;
        p = fmaf(p, w, 3.43273939e-07f);
        p = fmaf(p, w, -3.5233877e-06f);
        p = fmaf(p, w, -4.39150654e-06f);
        p = fmaf(p, w, 0.00021858087f);
        p = fmaf(p, w, -0.00125372503f);
        p = fmaf(p, w, -0.00417768164f);
        p = fmaf(p, w, 0.246640727f);
        p = fmaf(p, w, 1.50140941f);
    } else {
        w = sqrtf(w) - 3.0f;
        p = -0.000200214257f;
        p = fmaf(p, w, 0.000100950558f);
        p = fmaf(p, w, 0.00134934322f);
        p = fmaf(p, w, -0.00367342844f);
        p = fmaf(p, w, 0.00573950773f);
        p = fmaf(p, w, -0.0076224613f);
        p = fmaf(p, w, 0.00943887047f);
        p = fmaf(p, w, 1.00167406f);
        p = fmaf(p, w, 2.83297682f);
    }
    return __fmul_rn(p, x);
}

// normal sample from 32 random bits (jax uniform->erfinv path, exact)
__device__ __forceinline__ float normal_from_bits(uint32_t bits) {
    float f = __uint_as_float((bits >> 9) | 0x3f800000u) - 1.0f;  // [0,1)
    const float lo = -0.99999994f;  // nextafter(-1,0)
    float u = fmaxf(lo, __fadd_rn(__fmul_rn(f, 2.0f), lo));       // f*2 exact
    return __fmul_rn(1.41421356f, erfinv_xla(u));                 // 0x3FB504F3
}

// ---------------- small kernels --------------------------------------------
__global__ void k_init() {
    if (threadIdx.x < 4) g_max[threadIdx.x] = 0.0f;
}

__global__ void k_maxred(const float* __restrict__ x, int n, int slot) {
    float m = 0.0f;
    for (int i = blockIdx.x * blockDim.x + threadIdx.x; i < n;
         i += gridDim.x * blockDim.x)
        m = fmaxf(m, x[i]);
    for (int o = 16; o; o >>= 1)
        m = fmaxf(m, __shfl_xor_sync(0xffffffffu, m, o));
    if ((threadIdx.x & 31) == 0)
        atomicMax((int*)&g_max[slot], __float_as_int(m));  // m >= 0 always here
}

__device__ __forceinline__ float quant8(float x) {  // quant(x, 8, 1.0)
    float xs = fminf(fmaxf(x, -0.9921875f), 0.9921875f);
    return __fmul_rn(rintf(__fmul_rn(xs, 128.0f)), 0.0078125f);
}

// weff = quant(W,8,1) + (normal * max) * 0.1
__global__ void k_genw(const float* __restrict__ W, float* __restrict__ out,
                       int n, uint32_t k0, uint32_t k1, int maxslot) {
    int j = blockIdx.x * blockDim.x + threadIdx.x;
    if (j >= n) return;
    uint32_t o0, o1;
    tf2x32(k0, k1, 0u, (uint32_t)j, &o0, &o1);
    float nrm = normal_from_bits(o0 ^ o1);
    float wmax = g_max[maxslot];
    float noise = __fmul_rn(__fmul_rn(nrm, wmax), 0.1f);
    out[j] = __fadd_rn(quant8(W[j]), noise);
}

__global__ void k_genb(const float* __restrict__ bsrc, float* __restrict__ bq,
                       float* __restrict__ bn, int n,
                       uint32_t k0, uint32_t k1, int maxslot) {
    int j = blockIdx.x * blockDim.x + threadIdx.x;
    if (j >= n) return;
    uint32_t o0, o1;
    tf2x32(k0, k1, 0u, (uint32_t)j, &o0, &o1);
    float nrm = normal_from_bits(o0 ^ o1);
    float bmax = g_max[maxslot];
    bq[j] = quant8(bsrc[j]);
    bn[j] = __fmul_rn(__fmul_rn(nrm, bmax), 0.1f);
}

// code = int(rint(15 * (clip(x,+-ac)+off)/(2*ac))) & 15
__global__ void k_code(const float* __restrict__ x, unsigned char* __restrict__ code,
                       int n, const float* __restrict__ aclip,
                       const float* __restrict__ aoff) {
    int i = blockIdx.x * blockDim.x + threadIdx.x;
    if (i >= n) return;
    float ac = aclip[0], off = aoff[0];
    float denom = __fmul_rn(ac, 2.0f);
    float xc = fminf(fmaxf(x[i], -ac), ac);
    float v01 = __fdiv_rn(__fadd_rn(xc, off), denom);
    int v = (int)rintf(__fmul_rn(15.0f, v01));
    code[i] = (unsigned char)(v & 15);
}

// ---------------- packed f32x2 helpers --------------------------------------
__device__ __forceinline__ unsigned long long pk2(float x, float y) {
    unsigned long long r;
    asm("mov.b64 %0, {%1, %2};" : "=l"(r) : "f"(x), "f"(y));
    return r;
}
__device__ __forceinline__ void upk2(unsigned long long v, float& x, float& y) {
    asm("mov.b64 {%0, %1}, %2;" : "=f"(x), "=f"(y) : "l"(v));
}
__device__ __forceinline__ void fma2(unsigned long long& c, unsigned long long a,
                                     unsigned long long b) {
    asm("fma.rn.f32x2 %0, %1, %2, %0;" : "+l"(c) : "l"(a), "l"(b));
}

// ---------------- the plane-GEMM -------------------------------------------
// gates[b,n] (+)= (sum_m beta_m * (((sum_k bit_m(code[b,k])*weff[m,k,n]) + bq[m,n]) + bn[m,n] > 0.5)) * 2a - a
#define BM 128
#define BN 128
#define BKK 16

__global__ __launch_bounds__(256, 2)
void k_gemm(const unsigned char* __restrict__ codes, int K,
            const float* __restrict__ weff, const float* __restrict__ bq,
            const float* __restrict__ bn, const float* __restrict__ a_ptr,
            float* __restrict__ gates, int accumulate) {
    __shared__ float As[BKK][BM];
    __shared__ float Bs[BKK][BN];

    const int n0 = blockIdx.x * BN;
    const int b0 = blockIdx.y * BM;
    const int tid = threadIdx.x;
    const int tx = tid & 15, ty = tid >> 4;

    unsigned int res[8];
#pragma unroll
    for (int i = 0; i < 8; i++) res[i] = 0u;

    const int rowc = tid >> 1;
    const int kkbase = (tid & 1) * 8;

    for (int m = 0; m < 4; m++) {
        unsigned long long acc2[8][4];
#pragma unroll
        for (int i = 0; i < 8; i++)
#pragma unroll
            for (int j = 0; j < 4; j++) acc2[i][j] = 0ull;  // (+0.0f,+0.0f)

        const float* wm = weff + (size_t)m * K * N4H;
        const int shift = 3 - m;

        for (int kb = 0; kb < K; kb += BKK) {
            __syncthreads();
            // expand bit-plane m of the code tile into As (BKK x BM)
            {
                const unsigned char* src = codes + (size_t)(b0 + rowc) * K + kb + kkbase;
                uint64_t cc = *(const uint64_t*)src;   // 8B aligned
#pragma unroll
                for (int q = 0; q < 8; q++) {
                    unsigned int c = (unsigned int)(cc >> (8 * q)) & 0xffu;
                    As[kkbase + q][rowc] = (float)((c >> shift) & 1u);
                }
            }
            // load weight tile (BKK x BN)
            {
#pragma unroll
                for (int q = 0; q < 2; q++) {
                    int l4 = tid + q * 256;
                    int kk = l4 >> 5;
                    int nq = (l4 & 31) << 2;
                    float4 v = *reinterpret_cast<const float4*>(
                        wm + (size_t)(kb + kk) * N4H + n0 + nq);
                    *reinterpret_cast<float4*>(&Bs[kk][nq]) = v;
                }
            }
            __syncthreads();
#pragma unroll
            for (int k = 0; k < BKK; k++) {
                float a[8], b[8];
                *(float4*)&a[0] = *(float4*)&As[k][ty * 8];
                *(float4*)&a[4] = *(float4*)&As[k][ty * 8 + 4];
                *(float4*)&b[0] = *(float4*)&Bs[k][tx * 8];
                *(float4*)&b[4] = *(float4*)&Bs[k][tx * 8 + 4];
                unsigned long long a2[8], b2[4];
#pragma unroll
                for (int i = 0; i < 8; i++) a2[i] = pk2(a[i], a[i]);
#pragma unroll
                for (int j = 0; j < 4; j++) b2[j] = pk2(b[2 * j], b[2 * j + 1]);
#pragma unroll
                for (int i = 0; i < 8; i++)
#pragma unroll
                    for (int j = 0; j < 4; j++)
                        fma2(acc2[i][j], a2[i], b2[j]);
            }
        }
        // threshold epilogue for plane m -> pack as nibble bits
        const float* bqm = bq + m * N4H + n0 + tx * 8;
        const float* bnm = bn + m * N4H + n0 + tx * 8;
        float fq[8], fn[8];
#pragma unroll
        for (int j = 0; j < 8; j++) { fq[j] = bqm[j]; fn[j] = bnm[j]; }
#pragma unroll
        for (int i = 0; i < 8; i++) {
            float av[8];
#pragma unroll
            for (int j = 0; j < 4; j++) upk2(acc2[i][j], av[2 * j], av[2 * j + 1]);
            unsigned int w = 0;
#pragma unroll
            for (int j = 0; j < 8; j++) {
                float x = __fadd_rn(__fadd_rn(av[j], fq[j]), fn[j]);
                w |= (unsigned int)(x > 0.5f) << (4 * j);
            }
            res[i] += w << shift;
        }
    }

    // beta recombination (sequential m order matching XLA sum over axis 0)
    const float a = a_ptr[0];
    const float twoA = __fmul_rn(a, 2.0f);
    const float beta0 = 8.0f / 15.0f, beta1 = 4.0f / 15.0f;
    const float beta2 = 2.0f / 15.0f, beta3 = 1.0f / 15.0f;
#pragma unroll
    for (int i = 0; i < 8; i++) {
        int row = b0 + ty * 8 + i;
        float* gr = gates + (size_t)row * N4H + n0 + tx * 8;
#pragma unroll
        for (int j = 0; j < 8; j++) {
            unsigned int c = (res[i] >> (4 * j)) & 15u;
            float s = __fmul_rn(beta0, (float)((c >> 3) & 1u));
            s = __fadd_rn(s, __fmul_rn(beta1, (float)((c >> 2) & 1u)));
            s = __fadd_rn(s, __fmul_rn(beta2, (float)((c >> 1) & 1u)));
            s = __fadd_rn(s, __fmul_rn(beta3, (float)(c & 1u)));
            float part = __fsub_rn(__fmul_rn(s, twoA), a);
            gr[j] = accumulate ? __fadd_rn(gr[j], part) : part;
        }
    }
}

// ---------------- elementwise LSTM tail -------------------------------------
__device__ __forceinline__ float clipa(float x, float aa) {
    return fminf(fmaxf(x, -aa), aa);
}
__device__ __forceinline__ float quantf(float x, float r) {
    float xs = __fdiv_rn(x, r);
    xs = fminf(fmaxf(xs, -0.9921875f), 0.9921875f);
    float t = rintf(__fmul_rn(xs, 128.0f));
    return __fmul_rn(__fmul_rn(t, 0.0078125f), r);
}
__device__ __forceinline__ float sigm(float x) {   // XLA logistic expansion
    return __fadd_rn(0.5f, __fmul_rn(0.5f, tanhf(__fmul_rn(0.5f, x))));
}

__global__ void k_tail(const float* __restrict__ gates, const float* __restrict__ cx,
                       float* __restrict__ outh, float* __restrict__ outc,
                       const float* p3, const float* p4, const float* p5,
                       const float* p6, const float* p7, const float* p8,
                       const float* p9, const float* p10, const float* p11) {
    int idx = blockIdx.x * blockDim.x + threadIdx.x;
    if (idx >= B_ * H_) return;
    int b = idx >> 10;
    int h = idx & 1023;
    const float* g = gates + (size_t)b * N4H;
    float gi = g[h];
    float gj = g[H_ + h];
    float gf = g[2 * H_ + h];
    float go = g[3 * H_ + h];

    float a3 = p3[0], a4 = p4[0], a5 = p5[0], a6 = p6[0], a7 = p7[0];
    float a8 = p8[0], a9 = p9[0], a10 = p10[0], a11 = p11[0];

    float fg  = quantf(clipa(sigm(gf), a3), a3);
    float ig  = quantf(clipa(sigm(gi), a4), a4);
    float act = quantf(clipa(tanhf(gj), a5), a5);
    float og  = quantf(clipa(sigm(go), a6), a6);
    float gc  = quantf(clipa(__fmul_rn(cx[idx], fg), a7), a7);
    float ai  = quantf(clipa(__fmul_rn(ig, act), a8), a8);
    float nc  = quantf(clipa(__fadd_rn(gc, ai), a9), a9);
    float acl = quantf(clipa(tanhf(nc), a10), a10);
    float nh  = quantf(clipa(__fmul_rn(acl, og), a11), a11);
    outh[idx] = nh;
    outc[idx] = nc;
}

// ---------------- launch ----------------------------------------------------
extern "C" void kernel_launch(void* const* d_in, const int* in_sizes, int n_in,
                              void* d_out, int out_size) {
    const float* input = (const float*)d_in[0];
    const float* hx    = (const float*)d_in[1];
    const float* cx    = (const float*)d_in[2];
    const float* w_ih  = (const float*)d_in[3];
    const float* w_hh  = (const float*)d_in[4];
    const float* b_ih  = (const float*)d_in[5];
    const float* b_hh  = (const float*)d_in[6];
    const float* a1  = (const float*)d_in[7];
    const float* a3  = (const float*)d_in[8];
    const float* a4  = (const float*)d_in[9];
    const float* a5  = (const float*)d_in[10];
    const float* a6  = (const float*)d_in[11];
    const float* a7  = (const float*)d_in[12];
    const float* a8  = (const float*)d_in[13];
    const float* a9  = (const float*)d_in[14];
    const float* a10 = (const float*)d_in[15];
    const float* a11 = (const float*)d_in[16];
    float* outh = (float*)d_out;
    float* outc = (float*)d_out + (size_t)B_ * H_;

    // JAX key chain (partitionable/fold-like split), computed on host
    uint32_t k1a, k1b, k2a, k2b;
    tf2x32(0u, 42u, 0u, 0u, &k1a, &k1b);   // k1 = split(key(42))[0]
    tf2x32(0u, 42u, 0u, 1u, &k2a, &k2b);   // k2 = split(key(42))[1]
    uint32_t kw1a, kw1b, kb1a, kb1b, kw2a, kw2b, kb2a, kb2b;
    tf2x32(k1a, k1b, 0u, 0u, &kw1a, &kw1b);  // kw for ih
    tf2x32(k1a, k1b, 0u, 1u, &kb1a, &kb1b);  // kb for ih
    tf2x32(k2a, k2b, 0u, 0u, &kw2a, &kw2b);  // kw for hh
    tf2x32(k2a, k2b, 0u, 1u, &kb2a, &kb2b);  // kb for hh

    float *p_weff_ih, *p_weff_hh, *p_bq_ih, *p_bn_ih, *p_bq_hh, *p_bn_hh, *p_gates;
    unsigned char *p_code_in, *p_code_hx;
    cudaGetSymbolAddress((void**)&p_weff_ih, g_weff_ih);
    cudaGetSymbolAddress((void**)&p_weff_hh, g_weff_hh);
    cudaGetSymbolAddress((void**)&p_bq_ih, g_bq_ih);
    cudaGetSymbolAddress((void**)&p_bn_ih, g_bn_ih);
    cudaGetSymbolAddress((void**)&p_bq_hh, g_bq_hh);
    cudaGetSymbolAddress((void**)&p_bn_hh, g_bn_hh);
    cudaGetSymbolAddress((void**)&p_code_in, g_code_in);
    cudaGetSymbolAddress((void**)&p_code_hx, g_code_hx);
    cudaGetSymbolAddress((void**)&p_gates, g_gates);

    const int nwih = M_ * I_ * N4H;
    const int nwhh = M_ * H_ * N4H;
    const int nb = M_ * N4H;

    k_init<<<1, 32>>>();
    k_maxred<<<512, 256>>>(w_ih, nwih, 0);
    k_maxred<<<512, 256>>>(w_hh, nwhh, 1);
    k_maxred<<<64, 256>>>(b_ih, nb, 2);
    k_maxred<<<64, 256>>>(b_hh, nb, 3);

    k_genw<<<(nwih + 255) / 256, 256>>>(w_ih, p_weff_ih, nwih, kw1a, kw1b, 0);
    k_genw<<<(nwhh + 255) / 256, 256>>>(w_hh, p_weff_hh, nwhh, kw2a, kw2b, 1);
    k_genb<<<(nb + 255) / 256, 256>>>(b_ih, p_bq_ih, p_bn_ih, nb, kb1a, kb1b, 2);
    k_genb<<<(nb + 255) / 256, 256>>>(b_hh, p_bq_hh, p_bn_hh, nb, kb2a, kb2b, 3);

    k_code<<<(B_ * I_ + 255) / 256, 256>>>(input, p_code_in, B_ * I_, a1, a1);
    k_code<<<(B_ * H_ + 255) / 256, 256>>>(hx, p_code_hx, B_ * H_, a11, a1);

    dim3 grid(N4H / BN, B_ / BM);
    k_gemm<<<grid, 256>>>(p_code_in, I_, p_weff_ih, p_bq_ih, p_bn_ih, a1, p_gates, 0);
    k_gemm<<<grid, 256>>>(p_code_hx, H_, p_weff_hh, p_bq_hh, p_bn_hh, a11, p_gates, 1);

    k_tail<<<(B_ * H_ + 255) / 256, 256>>>(p_gates, cx, outh, outc,
                                           a3, a4, a5, a6, a7, a8, a9, a10, a11);
}